// round 1
// baseline (speedup 1.0000x reference)
#include <cuda_runtime.h>
#include <math.h>

// Upsample_910533066891: upfirdn2d up=2, k1d=[1,3,3,1]-style 4-tap separable FIR.
// x: [16,128,128,128] fp32 (NCHW), kernel_1d: [4] fp32.
// out: [16,128,H_out,H_out] fp32 with H_out = 255 per JAX lhs_dilation semantics
// (derived from out_size at launch so 256 would also work).
//
// Each output pixel = separable 2x2 weighted gather from input:
//   flipped normalized taps g[i] = k1d[3-i] * 2 / sum(k1d)
//   oy even -> rows oy/2-1, oy/2  with weights g0, g2
//   oy odd  -> rows (oy-1)/2, (oy+1)/2 with weights g1, g3
// (identically in x). Out-of-range taps get weight 0.

#define C_PLANES 2048           // 16 * 128
#define IN_H 128
#define IN_W 128
#define IN_PLANE (IN_H * IN_W)

__global__ __launch_bounds__(256, 8)
void up2x_kernel(const float* __restrict__ x,
                 const float* __restrict__ k,
                 float* __restrict__ out,
                 int out_h, int out_w)
{
    const int ox    = threadIdx.x;
    const int oy    = blockIdx.x;
    const int plane = blockIdx.y;          // n*C + c
    if (ox >= out_w) return;

    // Normalized flipped taps (4 const loads, L1/L2 resident after first warp).
    const float k0 = __ldg(k + 0), k1 = __ldg(k + 1);
    const float k2 = __ldg(k + 2), k3 = __ldg(k + 3);
    const float inv = 2.0f / (k0 + k1 + k2 + k3);
    const float g0 = k3 * inv, g1 = k2 * inv, g2 = k1 * inv, g3 = k0 * inv;

    // Row taps
    int r0 = (oy >> 1) - 1 + (oy & 1);     // == floor((oy-1)/2)
    int r1 = r0 + 1;
    float wy0 = (oy & 1) ? g1 : g0;
    float wy1 = (oy & 1) ? g3 : g2;
    if (r0 < 0)       { r0 = 0;        wy0 = 0.0f; }
    if (r1 >= IN_H)   { r1 = IN_H - 1; wy1 = 0.0f; }

    // Column taps
    int c0 = (ox >> 1) - 1 + (ox & 1);
    int c1 = c0 + 1;
    float wx0 = (ox & 1) ? g1 : g0;
    float wx1 = (ox & 1) ? g3 : g2;
    if (c0 < 0)       { c0 = 0;        wx0 = 0.0f; }
    if (c1 >= IN_W)   { c1 = IN_W - 1; wx1 = 0.0f; }

    const float* xp = x + (size_t)plane * IN_PLANE;
    const float a = __ldg(xp + r0 * IN_W + c0);
    const float b = __ldg(xp + r0 * IN_W + c1);
    const float c = __ldg(xp + r1 * IN_W + c0);
    const float d = __ldg(xp + r1 * IN_W + c1);

    const float v = wy0 * fmaf(wx0, a, wx1 * b) + wy1 * fmaf(wx0, c, wx1 * d);

    out[(size_t)plane * ((size_t)out_h * out_w) + (size_t)oy * out_w + ox] = v;
}

extern "C" void kernel_launch(void* const* d_in, const int* in_sizes, int n_in,
                              void* d_out, int out_size)
{
    const float* x = (const float*)d_in[0];
    const float* k = (const float*)d_in[1];
    float* out = (float*)d_out;

    // out_size = 2048 * H_out * W_out with H_out == W_out (255 per JAX semantics)
    const long long hw = (long long)out_size / C_PLANES;
    const int out_h = (int)llroundf(sqrtf((float)hw));
    const int out_w = out_h;

    dim3 grid(out_h, C_PLANES);
    up2x_kernel<<<grid, 256>>>(x, k, out, out_h, out_w);
}

// round 4
// speedup vs baseline: 3.1592x; 3.1592x over previous
#include <cuda_runtime.h>
#include <math.h>

// Upsample_910533066891: upfirdn2d up=2, 4-tap separable FIR, fp32 NCHW.
// x: [16,128,128,128], k1d: [4]. out: [16,128,255,255] (derived from out_size).
//
// Tiled kernel — each thread produces a 2x4 output block (8 outputs) from a
// 3x4 input neighborhood, amortizing weight computation, index math and guards.
// Separable: horizontal pass (2 parities x 4 rows), then vertical combine.
//
// Tap mapping (flipped, normalized g[i] = k1d[3-i]*2/sum):
//   ox even=2i -> cols i-1,i   weights g0,g2 ; ox odd=2i+1 -> cols i,i+1 w g1,g3
//   same in y. OOB taps handled by zeroing the loaded value.

#define IN_H 128
#define IN_W 128
#define C_PLANES 2048

__global__ __launch_bounds__(128, 8)
void up2x_tile_kernel(const float* __restrict__ x,
                      const float* __restrict__ kk,
                      float* __restrict__ out,
                      int out_h, int out_w)
{
    const int i     = threadIdx.x;        // column-pair index: outputs 2i, 2i+1
    const int j     = blockIdx.x * 2;     // input row base: outputs 2j .. 2j+3
    const int plane = blockIdx.y;         // n*C + c

    // Normalized flipped taps (amortized over 8 outputs)
    const float k0 = __ldg(kk + 0), k1 = __ldg(kk + 1);
    const float k2 = __ldg(kk + 2), k3 = __ldg(kk + 3);
    const float inv = 2.0f / (k0 + k1 + k2 + k3);
    const float g0 = k3 * inv, g1 = k2 * inv, g2 = k1 * inv, g3 = k0 * inv;

    const float* xp = x + (size_t)plane * (IN_H * IN_W);

    // 4 input rows (j-1 .. j+2) x 3 input cols (i-1 .. i+1); OOB -> 0
    float v[4][3];
#pragma unroll
    for (int r = 0; r < 4; ++r) {
        const int rr = j - 1 + r;
        const bool rok = (rr >= 0) && (rr < IN_H);
        const float* rowp = xp + rr * IN_W;
#pragma unroll
        for (int c = 0; c < 3; ++c) {
            const int cc = i - 1 + c;
            const bool ok = rok && (cc >= 0) && (cc < IN_W);
            v[r][c] = ok ? __ldg(rowp + cc) : 0.0f;
        }
    }

    // Horizontal pass: per row, even-x and odd-x partials
    float he[4], ho[4];
#pragma unroll
    for (int r = 0; r < 4; ++r) {
        he[r] = fmaf(g2, v[r][1], g0 * v[r][0]);
        ho[r] = fmaf(g3, v[r][2], g1 * v[r][1]);
    }

    // Vertical combine:
    //   oy=2j+0 (even,m=j)   : rows idx(0,1) w (g0,g2)
    //   oy=2j+1 (odd, m=j)   : rows idx(1,2) w (g1,g3)
    //   oy=2j+2 (even,m=j+1) : rows idx(1,2) w (g0,g2)
    //   oy=2j+3 (odd, m=j+1) : rows idx(2,3) w (g1,g3)
    float oe[4], oo[4];
    oe[0] = fmaf(g2, he[1], g0 * he[0]);  oo[0] = fmaf(g2, ho[1], g0 * ho[0]);
    oe[1] = fmaf(g3, he[2], g1 * he[1]);  oo[1] = fmaf(g3, ho[2], g1 * ho[1]);
    oe[2] = fmaf(g2, he[2], g0 * he[1]);  oo[2] = fmaf(g2, ho[2], g0 * ho[1]);
    oe[3] = fmaf(g3, he[3], g1 * he[2]);  oo[3] = fmaf(g3, ho[3], g1 * ho[2]);

    const int ox = 2 * i;
    const bool ox1_ok = (ox + 1) < out_w;
    size_t base = (size_t)plane * ((size_t)out_h * out_w)
                + (size_t)(2 * j) * out_w + ox;
#pragma unroll
    for (int t = 0; t < 4; ++t) {
        const int oy = 2 * j + t;
        if (oy < out_h) {
            out[base] = oe[t];
            if (ox1_ok) out[base + 1] = oo[t];
        }
        base += out_w;
    }
}

extern "C" void kernel_launch(void* const* d_in, const int* in_sizes, int n_in,
                              void* d_out, int out_size)
{
    const float* x = (const float*)d_in[0];
    const float* k = (const float*)d_in[1];
    float* out = (float*)d_out;

    // out_size = 2048 * H_out * W_out, H_out == W_out (255 per JAX semantics)
    const long long hw = (long long)out_size / C_PLANES;
    const int out_h = (int)llroundf(sqrtf((float)hw));
    const int out_w = out_h;

    dim3 grid((out_h + 3) / 4, C_PLANES);
    up2x_tile_kernel<<<grid, 128>>>(x, k, out, out_h, out_w);
}